// round 1
// baseline (speedup 1.0000x reference)
#include <cuda_runtime.h>

#define NN   50000
#define EE   800000
#define TT   4
#define HH   8
#define C1V  16
#define C2V  8
#define DD   128
#define HC1  128          // H*C1
#define HC2  64           // H*C2
#define OUTW 256          // T*H*C2
#define LRELU 0.2f

#define NB_SCAN 49        // ceil(50000/1024)

// ---------------- scratch (static device globals; no allocation) -------------
__device__ __align__(16) float g_h1 [NN * HC1];   // x @ W1[t]
__device__ __align__(16) float g_h1g[NN * HC1];   // GAT1 output (+relu)
__device__ __align__(16) float g_h2 [NN * HC2];   // h1g @ W2[t]
__device__ __align__(16) float g_ss [NN * HH];    // s_src
__device__ __align__(16) float g_sd [NN * HH];    // s_dst
__device__ int g_cnt [NN];
__device__ int g_offs[NN];
__device__ int g_cur [NN];
__device__ int g_eid [EE];
__device__ int g_aux [64];

// ---------------- CSR construction ------------------------------------------
__global__ void k_zero_cnt() {
    int i = blockIdx.x * blockDim.x + threadIdx.x;
    if (i < NN) g_cnt[i] = 0;
}

__global__ void k_count(const int* __restrict__ dst) {
    int e = blockIdx.x * blockDim.x + threadIdx.x;
    if (e < EE) atomicAdd(&g_cnt[dst[e]], 1);
}

__global__ void k_scan_block() {
    __shared__ int sh[1024];
    int i = blockIdx.x * 1024 + threadIdx.x;
    int v = (i < NN) ? g_cnt[i] : 0;
    sh[threadIdx.x] = v;
    __syncthreads();
    for (int d = 1; d < 1024; d <<= 1) {
        int t = (threadIdx.x >= d) ? sh[threadIdx.x - d] : 0;
        __syncthreads();
        sh[threadIdx.x] += t;
        __syncthreads();
    }
    if (i < NN) g_offs[i] = sh[threadIdx.x] - v;   // exclusive
    if (threadIdx.x == 1023) g_aux[blockIdx.x] = sh[1023];
}

__global__ void k_scan_aux() {
    if (threadIdx.x == 0) {
        int s = 0;
        for (int i = 0; i < NB_SCAN; i++) { int t = g_aux[i]; g_aux[i] = s; s += t; }
    }
}

__global__ void k_add_aux() {
    int i = blockIdx.x * 1024 + threadIdx.x;
    if (i < NN) {
        int v = g_offs[i] + g_aux[blockIdx.x];
        g_offs[i] = v;
        g_cur[i]  = v;
    }
}

__global__ void k_scatter(const int* __restrict__ dst) {
    int e = blockIdx.x * blockDim.x + threadIdx.x;
    if (e < EE) {
        int pos = atomicAdd(&g_cur[dst[e]], 1);
        g_eid[pos] = e;
    }
}

// ---------------- fp32 tiled GEMM: C[M,Nc] = A[M,K] @ B[K,Nc] ----------------
__global__ void k_gemm(const float* __restrict__ A, const float* __restrict__ B,
                       float* __restrict__ C, int M, int Nc, int K) {
    __shared__ float As[16][65];
    __shared__ float Bs[16][68];
    int tid = threadIdx.x;
    int rb = blockIdx.y * 64, cb = blockIdx.x * 64;
    int tx = tid & 15, ty = tid >> 4;
    float acc[4][4] = {};
    for (int k0 = 0; k0 < K; k0 += 16) {
        {   // A: 64 rows x 16 k
            int row = tid >> 2, kk = (tid & 3) * 4;
            int gr = rb + row;
            float4 v = make_float4(0.f, 0.f, 0.f, 0.f);
            if (gr < M) v = *(const float4*)&A[(size_t)gr * K + k0 + kk];
            As[kk + 0][row] = v.x; As[kk + 1][row] = v.y;
            As[kk + 2][row] = v.z; As[kk + 3][row] = v.w;
        }
        {   // B: 16 k x 64 cols
            int kk = tid >> 4, jb = (tid & 15) * 4;
            float4 v = *(const float4*)&B[(size_t)(k0 + kk) * Nc + cb + jb];
            *(float4*)&Bs[kk][jb] = v;
        }
        __syncthreads();
#pragma unroll
        for (int kk = 0; kk < 16; kk++) {
            float4 b4 = *(float4*)&Bs[kk][tx * 4];
            float b[4] = { b4.x, b4.y, b4.z, b4.w };
            float a[4];
#pragma unroll
            for (int i = 0; i < 4; i++) a[i] = As[kk][ty * 4 + i];
#pragma unroll
            for (int i = 0; i < 4; i++)
#pragma unroll
                for (int j = 0; j < 4; j++) acc[i][j] += a[i] * b[j];
        }
        __syncthreads();
    }
#pragma unroll
    for (int i = 0; i < 4; i++) {
        int gr = rb + ty * 4 + i;
        if (gr < M)
            *(float4*)&C[(size_t)gr * Nc + cb + tx * 4] =
                make_float4(acc[i][0], acc[i][1], acc[i][2], acc[i][3]);
    }
}

// ---------------- attention score precompute ---------------------------------
__global__ void k_scores(const float* __restrict__ feat,
                         const float* __restrict__ a_s, const float* __restrict__ a_d,
                         int C) {
    int idx = blockIdx.x * blockDim.x + threadIdx.x;
    if (idx >= NN * HH) return;
    int n = idx >> 3, hd = idx & 7;
    const float* f = &feat[(size_t)n * 8 * C + hd * C];
    float s1 = 0.f, s2 = 0.f;
    for (int c = 0; c < C; c++) {
        float v = f[c];
        s1 += v * a_s[hd * C + c];
        s2 += v * a_d[hd * C + c];
    }
    g_ss[idx] = s1;
    g_sd[idx] = s2;
}

// ---------------- GAT aggregation: one warp per node -------------------------
template <int C>
__global__ void k_gat(const float* __restrict__ feat,
                      const int* __restrict__ esrc, const int* __restrict__ etype,
                      int t, const float* __restrict__ bias,
                      float* __restrict__ out, int ostride, int ocol, int dorelu) {
    constexpr int HC = 8 * C;
    constexpr int VW = C / 4;               // 4 for C=16, 2 for C=8
    int gwarp = (blockIdx.x * blockDim.x + threadIdx.x) >> 5;
    if (gwarp >= NN) return;
    int lane = threadIdx.x & 31;
    int node = gwarp;
    int start = g_offs[node];
    int deg   = g_cnt[node];

    // ---- pass 1: per-head max (lane&7 = head, 4 edge slots) ----
    int h1 = lane & 7;
    float sd1 = g_sd[node * 8 + h1];
    float v0 = g_ss[node * 8 + h1] + sd1;            // self-loop logit
    float mx = v0 > 0.f ? v0 : LRELU * v0;
    for (int i = (lane >> 3); i < deg; i += 4) {
        int e = g_eid[start + i];
        if (etype[e] == t) {
            int s = esrc[e];
            float u = g_ss[s * 8 + h1] + sd1;
            u = u > 0.f ? u : LRELU * u;
            mx = fmaxf(mx, u);
        }
    }
    mx = fmaxf(mx, __shfl_xor_sync(0xffffffffu, mx, 8));
    mx = fmaxf(mx, __shfl_xor_sync(0xffffffffu, mx, 16));

    // ---- pass 2: softmax + weighted aggregation ----
    int hd = lane >> 2;
    int cbase = (lane & 3) * VW;
    float m_h  = __shfl_sync(0xffffffffu, mx, hd);
    float sd_h = g_sd[node * 8 + hd];

    float es = g_ss[node * 8 + hd] + sd_h;           // self loop
    es = es > 0.f ? es : LRELU * es;
    float p = __expf(es - m_h);
    float denom = ((lane & 3) == 0) ? p : 0.f;

    float acc[VW];
    {
        const float* fp = &feat[(size_t)node * HC + hd * C + cbase];
        if constexpr (VW == 4) {
            float4 hv = *(const float4*)fp;
            acc[0] = p * hv.x; acc[1] = p * hv.y; acc[2] = p * hv.z; acc[3] = p * hv.w;
        } else {
            float2 hv = *(const float2*)fp;
            acc[0] = p * hv.x; acc[1] = p * hv.y;
        }
    }

    for (int i = 0; i < deg; i++) {
        int e = g_eid[start + i];
        if (etype[e] != t) continue;
        int s = esrc[e];
        float u = g_ss[s * 8 + hd] + sd_h;
        u = u > 0.f ? u : LRELU * u;
        float pe = __expf(u - m_h);
        if ((lane & 3) == 0) denom += pe;
        const float* fp = &feat[(size_t)s * HC + hd * C + cbase];
        if constexpr (VW == 4) {
            float4 hv = *(const float4*)fp;
            acc[0] += pe * hv.x; acc[1] += pe * hv.y;
            acc[2] += pe * hv.z; acc[3] += pe * hv.w;
        } else {
            float2 hv = *(const float2*)fp;
            acc[0] += pe * hv.x; acc[1] += pe * hv.y;
        }
    }

    denom = __shfl_sync(0xffffffffu, denom, lane & ~3);
    float inv = 1.f / denom;
    float* op = &out[(size_t)node * ostride + ocol + hd * C + cbase];
    if constexpr (VW == 4) {
        float4 o;
        o.x = acc[0] * inv + bias[hd * C + cbase + 0];
        o.y = acc[1] * inv + bias[hd * C + cbase + 1];
        o.z = acc[2] * inv + bias[hd * C + cbase + 2];
        o.w = acc[3] * inv + bias[hd * C + cbase + 3];
        if (dorelu) {
            o.x = fmaxf(o.x, 0.f); o.y = fmaxf(o.y, 0.f);
            o.z = fmaxf(o.z, 0.f); o.w = fmaxf(o.w, 0.f);
        }
        *(float4*)op = o;
    } else {
        float2 o;
        o.x = acc[0] * inv + bias[hd * C + cbase + 0];
        o.y = acc[1] * inv + bias[hd * C + cbase + 1];
        if (dorelu) { o.x = fmaxf(o.x, 0.f); o.y = fmaxf(o.y, 0.f); }
        *(float2*)op = o;
    }
}

// ---------------- launch ------------------------------------------------------
extern "C" void kernel_launch(void* const* d_in, const int* in_sizes, int n_in,
                              void* d_out, int out_size) {
    const float* x     = (const float*)d_in[0];
    const int*   esrc  = (const int*)  d_in[1];
    const int*   edst  = (const int*)  d_in[2];
    const int*   etype = (const int*)  d_in[3];
    const float* W1    = (const float*)d_in[4];
    const float* a1s   = (const float*)d_in[5];
    const float* a1d   = (const float*)d_in[6];
    const float* b1    = (const float*)d_in[7];
    const float* W2    = (const float*)d_in[8];
    const float* a2s   = (const float*)d_in[9];
    const float* a2d   = (const float*)d_in[10];
    const float* b2    = (const float*)d_in[11];
    float* out = (float*)d_out;

    float *p_h1, *p_h1g, *p_h2;
    cudaGetSymbolAddress((void**)&p_h1,  g_h1);
    cudaGetSymbolAddress((void**)&p_h1g, g_h1g);
    cudaGetSymbolAddress((void**)&p_h2,  g_h2);

    // --- CSR build ---
    k_zero_cnt<<<(NN + 255) / 256, 256>>>();
    k_count<<<(EE + 255) / 256, 256>>>(edst);
    k_scan_block<<<NB_SCAN, 1024>>>();
    k_scan_aux<<<1, 32>>>();
    k_add_aux<<<NB_SCAN, 1024>>>();
    k_scatter<<<(EE + 255) / 256, 256>>>(edst);

    const int gat_blocks = (NN * 32 + 255) / 256;

    for (int t = 0; t < TT; t++) {
        // layer 1: h1 = x @ W1[t]
        {
            dim3 grid(HC1 / 64, (NN + 63) / 64);
            k_gemm<<<grid, 256>>>(x, W1 + (size_t)t * DD * HC1, p_h1, NN, HC1, DD);
        }
        k_scores<<<(NN * HH + 255) / 256, 256>>>(p_h1, a1s + t * HH * C1V,
                                                 a1d + t * HH * C1V, C1V);
        k_gat<C1V><<<gat_blocks, 256>>>(p_h1, esrc, etype, t,
                                        b1 + t * HC1, p_h1g, HC1, 0, 1);
        // layer 2: h2 = h1g @ W2[t]
        {
            dim3 grid(HC2 / 64, (NN + 63) / 64);
            k_gemm<<<grid, 256>>>(p_h1g, W2 + (size_t)t * HC1 * HC2, p_h2, NN, HC2, HC1);
        }
        k_scores<<<(NN * HH + 255) / 256, 256>>>(p_h2, a2s + t * HH * C2V,
                                                 a2d + t * HH * C2V, C2V);
        k_gat<C2V><<<gat_blocks, 256>>>(p_h2, esrc, etype, t,
                                        b2 + t * HC2, out, OUTW, t * HC2, 0);
    }
}

// round 6
// speedup vs baseline: 1.1167x; 1.1167x over previous
#include <cuda_runtime.h>
#include <cuda_bf16.h>
#include <cstdint>

#define NN   50000
#define EE   800000
#define TT   4
#define HH   8
#define C1V  16
#define C2V  8
#define DD   128
#define HC1  128          // H*C1
#define HC2  64           // H*C2
#define OUTW 256          // T*H*C2
#define LRELU 0.2f

#define NB_SCAN 49        // ceil(50000/1024)
#define MTILES  391       // ceil(50000/128)

// ---------------- scratch (static device globals; no allocation) -------------
__device__ __align__(16) float g_h1 [NN * HC1];            // current-t GEMM1 out
__device__ __align__(16) float g_h2 [NN * HC2];            // current-t GEMM2 out
__device__ __align__(16) float g_ss [NN * HH];
__device__ __align__(16) float g_sd [NN * HH];
__device__ __align__(16) __nv_bfloat16 g_xh [NN * DD];     // x split hi
__device__ __align__(16) __nv_bfloat16 g_xl [NN * DD];     // x split lo
__device__ __align__(16) __nv_bfloat16 g_h1gh[NN * HC1];   // GAT1 out split hi
__device__ __align__(16) __nv_bfloat16 g_h1gl[NN * HC1];   // GAT1 out split lo
__device__ __align__(16) __nv_bfloat16 gW1h[TT * HC1 * DD];   // W1^T hi  [t][n][k]
__device__ __align__(16) __nv_bfloat16 gW1l[TT * HC1 * DD];   // W1^T lo
__device__ __align__(16) __nv_bfloat16 gW2h[TT * HC2 * HC1];  // W2^T hi
__device__ __align__(16) __nv_bfloat16 gW2l[TT * HC2 * HC1];  // W2^T lo
__device__ int g_cnt [NN];
__device__ int g_offs[NN];
__device__ int g_cur [NN];
__device__ int g_eid [EE];
__device__ int g_aux [64];

// ============================ helpers ========================================
__device__ __forceinline__ uint32_t smem_u32(const void* p) {
    uint32_t a;
    asm("{ .reg .u64 t; cvta.to.shared.u64 t, %1; cvt.u32.u64 %0, t; }"
        : "=r"(a) : "l"(p));
    return a;
}

#define LDMX4(r0, r1, r2, r3, addr) \
    asm volatile("ldmatrix.sync.aligned.m8n8.x4.shared.b16 {%0,%1,%2,%3}, [%4];" \
        : "=r"(r0), "=r"(r1), "=r"(r2), "=r"(r3) : "r"(addr))

__device__ __forceinline__ void mma_bf16(float& c0, float& c1, float& c2, float& c3,
                                         uint32_t a0, uint32_t a1, uint32_t a2, uint32_t a3,
                                         uint32_t b0, uint32_t b1) {
    asm volatile(
        "mma.sync.aligned.m16n8k16.row.col.f32.bf16.bf16.f32 "
        "{%0,%1,%2,%3}, {%4,%5,%6,%7}, {%8,%9}, {%0,%1,%2,%3};"
        : "+f"(c0), "+f"(c1), "+f"(c2), "+f"(c3)
        : "r"(a0), "r"(a1), "r"(a2), "r"(a3), "r"(b0), "r"(b1));
}

// ---------------- CSR construction ------------------------------------------
__global__ void k_zero_cnt() {
    int i = blockIdx.x * blockDim.x + threadIdx.x;
    if (i < NN) g_cnt[i] = 0;
}

__global__ void k_count(const int* __restrict__ dst) {
    int e = blockIdx.x * blockDim.x + threadIdx.x;
    if (e < EE) atomicAdd(&g_cnt[dst[e]], 1);
}

__global__ void k_scan_block() {
    __shared__ int sh[1024];
    int i = blockIdx.x * 1024 + threadIdx.x;
    int v = (i < NN) ? g_cnt[i] : 0;
    sh[threadIdx.x] = v;
    __syncthreads();
    for (int d = 1; d < 1024; d <<= 1) {
        int t = (threadIdx.x >= d) ? sh[threadIdx.x - d] : 0;
        __syncthreads();
        sh[threadIdx.x] += t;
        __syncthreads();
    }
    if (i < NN) g_offs[i] = sh[threadIdx.x] - v;   // exclusive
    if (threadIdx.x == 1023) g_aux[blockIdx.x] = sh[1023];
}

__global__ void k_scan_aux() {
    if (threadIdx.x == 0) {
        int s = 0;
        for (int i = 0; i < NB_SCAN; i++) { int t = g_aux[i]; g_aux[i] = s; s += t; }
    }
}

__global__ void k_add_aux() {
    int i = blockIdx.x * 1024 + threadIdx.x;
    if (i < NN) {
        int v = g_offs[i] + g_aux[blockIdx.x];
        g_offs[i] = v;
        g_cur[i]  = v;
    }
}

__global__ void k_scatter(const int* __restrict__ dst) {
    int e = blockIdx.x * blockDim.x + threadIdx.x;
    if (e < EE) {
        int pos = atomicAdd(&g_cur[dst[e]], 1);
        g_eid[pos] = e;
    }
}

// ---------------- weight transpose + bf16 hi/lo split -------------------------
__global__ void k_transW(const float* __restrict__ W1, const float* __restrict__ W2) {
    int i = blockIdx.x * blockDim.x + threadIdx.x;
    const int N1 = TT * HC1 * DD;   // 65536
    const int N2 = TT * HC2 * HC1;  // 32768
    if (i < N1) {
        int t = i >> 14, r = i & 16383;
        int n = r >> 7, k = r & 127;
        float v = W1[(t << 14) + k * HC1 + n];
        __nv_bfloat16 h = __float2bfloat16(v);
        gW1h[i] = h;
        gW1l[i] = __float2bfloat16(v - __bfloat162float(h));
    } else if (i < N1 + N2) {
        int j = i - N1;
        int t = j >> 13, r = j & 8191;
        int n = r >> 7, k = r & 127;
        float v = W2[t * 8192 + k * HC2 + n];
        __nv_bfloat16 h = __float2bfloat16(v);
        gW2h[j] = h;
        gW2l[j] = __float2bfloat16(v - __bfloat162float(h));
    }
}

// ---------------- x split ----------------------------------------------------
__global__ void k_split_x(const float* __restrict__ x) {
    int i = blockIdx.x * blockDim.x + threadIdx.x;
    if (i < NN * DD) {
        float v = x[i];
        __nv_bfloat16 h = __float2bfloat16(v);
        g_xh[i] = h;
        g_xl[i] = __float2bfloat16(v - __bfloat162float(h));
    }
}

// ---------------- HMMA bf16-split GEMM ---------------------------------------
// C[m][NT] = A[m][0:128] @ B[NT][128]^T, 3-term bf16 split, fp32 accumulate.
// A: pre-split bf16 hi/lo [M][128]; B: pre-split bf16 hi/lo [NT][128] (n-major).
// Block: 256 thr (8 warps), tile M=128 x N=NT.  Warp tile: 64 x (NT/4).
template <int NT>
__global__ void __launch_bounds__(256, 1)
k_gemm_mma(const __nv_bfloat16* __restrict__ Ah, const __nv_bfloat16* __restrict__ Al,
           const __nv_bfloat16* __restrict__ Bh, const __nv_bfloat16* __restrict__ Bl,
           float* __restrict__ C, int M) {
    constexpr int K    = 128;
    constexpr int STRB = 272;                 // padded row stride in bytes (136 bf16)
    constexpr int ASZ  = 128 * STRB;          // 34816 bytes per A tile
    constexpr int BSZ  = NT  * STRB;
    constexpr int NW   = NT / 4;              // cols per warp (32 or 16)
    constexpr int NF   = NW / 8;              // n8 frags per warp (4 or 2)

    extern __shared__ __align__(16) char smem[];
    uint32_t sb = smem_u32(smem);
    const uint32_t As = sb;                   // A hi ; +ASZ = A lo
    const uint32_t Bs = sb + 2 * ASZ;         // B hi ; +BSZ = B lo

    int tid = threadIdx.x, wid = tid >> 5, lane = tid & 31;
    int m0 = blockIdx.x * 128;

    // ---- load tiles (16B chunks) ----
    {
        // A: 128 rows x 16 chunks
        for (int idx = tid; idx < 128 * 16; idx += 256) {
            int row = idx >> 4, c = idx & 15;
            int gm = m0 + row;
            uint4 vh = make_uint4(0, 0, 0, 0), vl = vh;
            if (gm < M) {
                vh = *(const uint4*)&Ah[(size_t)gm * K + c * 8];
                vl = *(const uint4*)&Al[(size_t)gm * K + c * 8];
            }
            char* ph = smem + row * STRB + c * 16;
            *(uint4*)ph = vh;
            *(uint4*)(ph + ASZ) = vl;
        }
        // B: NT rows x 16 chunks
        for (int idx = tid; idx < NT * 16; idx += 256) {
            int row = idx >> 4, c = idx & 15;
            uint4 vh = *(const uint4*)&Bh[(size_t)row * K + c * 8];
            uint4 vl = *(const uint4*)&Bl[(size_t)row * K + c * 8];
            char* ph = smem + 2 * ASZ + row * STRB + c * 16;
            *(uint4*)ph = vh;
            *(uint4*)(ph + BSZ) = vl;
        }
    }
    __syncthreads();

    int warpM = wid >> 2;        // 0..1  (64 rows each)
    int warpN = wid & 3;         // 0..3  (NW cols each)
    int lr = lane & 7, lg = lane >> 3;

    // per-lane ldmatrix address components
    uint32_t aRow = warpM * 64 + lr + (lg & 1) * 8;   // + mf*16
    uint32_t aCol = (lg >> 1) * 8;                    // elems
    uint32_t bRow = warpN * NW + lr + (lg >> 1) * 8;  // + nf2*16
    uint32_t bCol = (lg & 1) * 8;

    float c[4][NF][4];
#pragma unroll
    for (int mf = 0; mf < 4; mf++)
#pragma unroll
        for (int nf = 0; nf < NF; nf++)
#pragma unroll
            for (int j = 0; j < 4; j++) c[mf][nf][j] = 0.f;

#pragma unroll
    for (int p = 0; p < 3; p++) {
        uint32_t Abase = As + ((p == 2) ? ASZ : 0);
        uint32_t Bbase = Bs + ((p == 1) ? BSZ : 0);
#pragma unroll
        for (int ks = 0; ks < 8; ks++) {
            int k0 = ks * 16;
            uint32_t a[4][4];
#pragma unroll
            for (int mf = 0; mf < 4; mf++) {
                uint32_t ad = Abase + (aRow + mf * 16) * STRB + (k0 + aCol) * 2;
                LDMX4(a[mf][0], a[mf][1], a[mf][2], a[mf][3], ad);
            }
            uint32_t b[NF][2];
#pragma unroll
            for (int nf2 = 0; nf2 < NF / 2; nf2++) {
                uint32_t bd = Bbase + (bRow + nf2 * 16) * STRB + (k0 + bCol) * 2;
                uint32_t r0, r1, r2, r3;
                LDMX4(r0, r1, r2, r3, bd);
                b[2 * nf2][0] = r0; b[2 * nf2][1] = r1;
                b[2 * nf2 + 1][0] = r2; b[2 * nf2 + 1][1] = r3;
            }
#pragma unroll
            for (int mf = 0; mf < 4; mf++)
#pragma unroll
                for (int nf = 0; nf < NF; nf++)
                    mma_bf16(c[mf][nf][0], c[mf][nf][1], c[mf][nf][2], c[mf][nf][3],
                             a[mf][0], a[mf][1], a[mf][2], a[mf][3],
                             b[nf][0], b[nf][1]);
        }
    }

    // ---- epilogue ----
    int g = lane >> 2, tq = lane & 3;
#pragma unroll
    for (int mf = 0; mf < 4; mf++) {
        int m = m0 + warpM * 64 + mf * 16 + g;
#pragma unroll
        for (int nf = 0; nf < NF; nf++) {
            int n = warpN * NW + nf * 8 + tq * 2;
            if (m < M)
                *(float2*)&C[(size_t)m * NT + n] = make_float2(c[mf][nf][0], c[mf][nf][1]);
            if (m + 8 < M)
                *(float2*)&C[(size_t)(m + 8) * NT + n] = make_float2(c[mf][nf][2], c[mf][nf][3]);
        }
    }
}

// ---------------- attention score precompute ---------------------------------
__global__ void k_scores(const float* __restrict__ feat,
                         const float* __restrict__ a_s, const float* __restrict__ a_d,
                         int C) {
    int idx = blockIdx.x * blockDim.x + threadIdx.x;
    if (idx >= NN * HH) return;
    int n = idx >> 3, hd = idx & 7;
    const float* f = &feat[(size_t)n * 8 * C + hd * C];
    float s1 = 0.f, s2 = 0.f;
    for (int c = 0; c < C; c++) {
        float v = f[c];
        s1 += v * a_s[hd * C + c];
        s2 += v * a_d[hd * C + c];
    }
    g_ss[idx] = s1;
    g_sd[idx] = s2;
}

// ---------------- GAT aggregation: one warp per node -------------------------
// BF16OUT: write bf16 hi/lo split (layer-1 path, with relu) instead of fp32.
template <int C, bool BF16OUT>
__global__ void k_gat(const float* __restrict__ feat,
                      const int* __restrict__ esrc, const int* __restrict__ etype,
                      int t, const float* __restrict__ bias,
                      float* __restrict__ out, int ostride, int ocol,
                      __nv_bfloat16* __restrict__ outh,
                      __nv_bfloat16* __restrict__ outl, int dorelu) {
    constexpr int HC = 8 * C;
    constexpr int VW = C / 4;               // 4 for C=16, 2 for C=8
    int gwarp = (blockIdx.x * blockDim.x + threadIdx.x) >> 5;
    if (gwarp >= NN) return;
    int lane = threadIdx.x & 31;
    int node = gwarp;
    int start = g_offs[node];
    int deg   = g_cnt[node];

    // ---- pass 1: per-head max (lane&7 = head, 4 edge slots) ----
    int h1 = lane & 7;
    float sd1 = g_sd[node * 8 + h1];
    float v0 = g_ss[node * 8 + h1] + sd1;            // self-loop logit
    float mx = v0 > 0.f ? v0 : LRELU * v0;
    for (int i = (lane >> 3); i < deg; i += 4) {
        int e = g_eid[start + i];
        if (etype[e] == t) {
            int s = esrc[e];
            float u = g_ss[s * 8 + h1] + sd1;
            u = u > 0.f ? u : LRELU * u;
            mx = fmaxf(mx, u);
        }
    }
    mx = fmaxf(mx, __shfl_xor_sync(0xffffffffu, mx, 8));
    mx = fmaxf(mx, __shfl_xor_sync(0xffffffffu, mx, 16));

    // ---- pass 2: softmax + weighted aggregation ----
    int hd = lane >> 2;
    int cbase = (lane & 3) * VW;
    float m_h  = __shfl_sync(0xffffffffu, mx, hd);
    float sd_h = g_sd[node * 8 + hd];

    float es = g_ss[node * 8 + hd] + sd_h;           // self loop
    es = es > 0.f ? es : LRELU * es;
    float p = __expf(es - m_h);
    float denom = ((lane & 3) == 0) ? p : 0.f;

    float acc[VW];
    {
        const float* fp = &feat[(size_t)node * HC + hd * C + cbase];
        if constexpr (VW == 4) {
            float4 hv = *(const float4*)fp;
            acc[0] = p * hv.x; acc[1] = p * hv.y; acc[2] = p * hv.z; acc[3] = p * hv.w;
        } else {
            float2 hv = *(const float2*)fp;
            acc[0] = p * hv.x; acc[1] = p * hv.y;
        }
    }

    for (int i = 0; i < deg; i++) {
        int e = g_eid[start + i];
        if (etype[e] != t) continue;
        int s = esrc[e];
        float u = g_ss[s * 8 + hd] + sd_h;
        u = u > 0.f ? u : LRELU * u;
        float pe = __expf(u - m_h);
        if ((lane & 3) == 0) denom += pe;
        const float* fp = &feat[(size_t)s * HC + hd * C + cbase];
        if constexpr (VW == 4) {
            float4 hv = *(const float4*)fp;
            acc[0] += pe * hv.x; acc[1] += pe * hv.y;
            acc[2] += pe * hv.z; acc[3] += pe * hv.w;
        } else {
            float2 hv = *(const float2*)fp;
            acc[0] += pe * hv.x; acc[1] += pe * hv.y;
        }
    }

    denom = __shfl_sync(0xffffffffu, denom, lane & ~3);
    float inv = 1.f / denom;
    float o[VW];
#pragma unroll
    for (int j = 0; j < VW; j++) {
        float v = acc[j] * inv + bias[hd * C + cbase + j];
        if (dorelu) v = fmaxf(v, 0.f);
        o[j] = v;
    }
    if constexpr (BF16OUT) {
        size_t ob = (size_t)node * HC + hd * C + cbase;
#pragma unroll
        for (int j = 0; j < VW; j += 2) {
            __nv_bfloat16 h0 = __float2bfloat16(o[j]);
            __nv_bfloat16 h1b = __float2bfloat16(o[j + 1]);
            __nv_bfloat162 hp; hp.x = h0; hp.y = h1b;
            __nv_bfloat162 lp;
            lp.x = __float2bfloat16(o[j] - __bfloat162float(h0));
            lp.y = __float2bfloat16(o[j + 1] - __bfloat162float(h1b));
            *(__nv_bfloat162*)&outh[ob + j] = hp;
            *(__nv_bfloat162*)&outl[ob + j] = lp;
        }
    } else {
        float* op = &out[(size_t)node * ostride + ocol + hd * C + cbase];
        if constexpr (VW == 4) {
            *(float4*)op = make_float4(o[0], o[1], o[2], o[3]);
        } else {
            *(float2*)op = make_float2(o[0], o[1]);
        }
    }
}

// ---------------- launch ------------------------------------------------------
extern "C" void kernel_launch(void* const* d_in, const int* in_sizes, int n_in,
                              void* d_out, int out_size) {
    const float* x     = (const float*)d_in[0];
    const int*   esrc  = (const int*)  d_in[1];
    const int*   edst  = (const int*)  d_in[2];
    const int*   etype = (const int*)  d_in[3];
    const float* W1    = (const float*)d_in[4];
    const float* a1s   = (const float*)d_in[5];
    const float* a1d   = (const float*)d_in[6];
    const float* b1    = (const float*)d_in[7];
    const float* W2    = (const float*)d_in[8];
    const float* a2s   = (const float*)d_in[9];
    const float* a2d   = (const float*)d_in[10];
    const float* b2    = (const float*)d_in[11];
    float* out = (float*)d_out;

    float *p_h1, *p_h2;
    __nv_bfloat16 *pW1h, *pW1l, *pW2h, *pW2l, *p_xh, *p_xl, *p_h1gh, *p_h1gl;
    cudaGetSymbolAddress((void**)&p_h1,   g_h1);
    cudaGetSymbolAddress((void**)&p_h2,   g_h2);
    cudaGetSymbolAddress((void**)&pW1h,   gW1h);
    cudaGetSymbolAddress((void**)&pW1l,   gW1l);
    cudaGetSymbolAddress((void**)&pW2h,   gW2h);
    cudaGetSymbolAddress((void**)&pW2l,   gW2l);
    cudaGetSymbolAddress((void**)&p_xh,   g_xh);
    cudaGetSymbolAddress((void**)&p_xl,   g_xl);
    cudaGetSymbolAddress((void**)&p_h1gh, g_h1gh);
    cudaGetSymbolAddress((void**)&p_h1gl, g_h1gl);

    const int ASZ = 128 * 272;
    const int smem1 = 2 * ASZ + 2 * 128 * 272;   // 139264
    const int smem2 = 2 * ASZ + 2 * 64 * 272;    // 104448
    cudaFuncSetAttribute(k_gemm_mma<HC1>, cudaFuncAttributeMaxDynamicSharedMemorySize, smem1);
    cudaFuncSetAttribute(k_gemm_mma<HC2>, cudaFuncAttributeMaxDynamicSharedMemorySize, smem2);

    // --- CSR build ---
    k_zero_cnt<<<(NN + 255) / 256, 256>>>();
    k_count<<<(EE + 255) / 256, 256>>>(edst);
    k_scan_block<<<NB_SCAN, 1024>>>();
    k_scan_aux<<<1, 32>>>();
    k_add_aux<<<NB_SCAN, 1024>>>();
    k_scatter<<<(EE + 255) / 256, 256>>>(edst);

    // --- weight transpose + bf16 splits ---
    k_transW<<<(TT * HC1 * DD + TT * HC2 * HC1 + 255) / 256, 256>>>(W1, W2);
    k_split_x<<<(NN * DD + 255) / 256, 256>>>(x);

    const int gat_blocks = (NN * 32 + 255) / 256;

    for (int t = 0; t < TT; t++) {
        // layer 1: h1 = x @ W1[t]
        k_gemm_mma<HC1><<<MTILES, 256, smem1>>>(p_xh, p_xl,
                                                pW1h + (size_t)t * HC1 * DD,
                                                pW1l + (size_t)t * HC1 * DD,
                                                p_h1, NN);
        k_scores<<<(NN * HH + 255) / 256, 256>>>(p_h1, a1s + t * HH * C1V,
                                                 a1d + t * HH * C1V, C1V);
        // GAT1 -> bf16 split output (relu fused)
        k_gat<C1V, true><<<gat_blocks, 256>>>(p_h1, esrc, etype, t, b1 + t * HC1,
                                              nullptr, 0, 0, p_h1gh, p_h1gl, 1);
        // layer 2: h2 = h1g @ W2[t]
        k_gemm_mma<HC2><<<MTILES, 256, smem2>>>(p_h1gh, p_h1gl,
                                                pW2h + (size_t)t * HC2 * HC1,
                                                pW2l + (size_t)t * HC2 * HC1,
                                                p_h2, NN);
        k_scores<<<(NN * HH + 255) / 256, 256>>>(p_h2, a2s + t * HH * C2V,
                                                 a2d + t * HH * C2V, C2V);
        // GAT2 -> final output slice
        k_gat<C2V, false><<<gat_blocks, 256>>>(p_h2, esrc, etype, t, b2 + t * HC2,
                                               out, OUTW, t * HC2, nullptr, nullptr, 0);
    }
}

// round 7
// speedup vs baseline: 1.7723x; 1.5872x over previous
#include <cuda_runtime.h>
#include <cuda_bf16.h>
#include <cstdint>

#define NN   50000
#define EE   800000
#define TT   4
#define HH   8
#define C1V  16
#define C2V  8
#define DD   128
#define HC1  128          // H*C1
#define HC2  64           // H*C2
#define OUTW 256          // T*H*C2
#define LRELU 0.2f

#define NSEG (NN * TT)    // 200000 (type,node) segments
#define NB2  196          // ceil(NSEG/1024)
#define MTILES 391        // ceil(50000/128)

// ---------------- scratch (static device globals; no allocation) -------------
__device__ __align__(16) float g_h1 [TT * NN * HC1];       // GEMM1 out (all t)
__device__ __align__(16) float g_h2 [TT * NN * HC2];       // GEMM2 out (all t)
__device__ __align__(16) float g_ss [TT * NN * HH];
__device__ __align__(16) float g_sd [TT * NN * HH];
__device__ __align__(16) __nv_bfloat16 g_xh [NN * DD];
__device__ __align__(16) __nv_bfloat16 g_xl [NN * DD];
__device__ __align__(16) __nv_bfloat16 g_h1gh[TT * NN * HC1];
__device__ __align__(16) __nv_bfloat16 g_h1gl[TT * NN * HC1];
__device__ __align__(16) __nv_bfloat16 gW1h[TT * HC1 * DD];
__device__ __align__(16) __nv_bfloat16 gW1l[TT * HC1 * DD];
__device__ __align__(16) __nv_bfloat16 gW2h[TT * HC2 * HC1];
__device__ __align__(16) __nv_bfloat16 gW2l[TT * HC2 * HC1];
__device__ int g_cnt [NSEG];
__device__ int g_offs[NSEG];
__device__ int g_cur [NSEG];
__device__ int g_src [EE];     // source node ids, sorted by (type,dst)
__device__ int g_aux [256];

// ============================ helpers ========================================
__device__ __forceinline__ uint32_t smem_u32(const void* p) {
    uint32_t a;
    asm("{ .reg .u64 t; cvta.to.shared.u64 t, %1; cvt.u32.u64 %0, t; }"
        : "=r"(a) : "l"(p));
    return a;
}

#define LDMX4(r0, r1, r2, r3, addr) \
    asm volatile("ldmatrix.sync.aligned.m8n8.x4.shared.b16 {%0,%1,%2,%3}, [%4];" \
        : "=r"(r0), "=r"(r1), "=r"(r2), "=r"(r3) : "r"(addr))

__device__ __forceinline__ void mma_bf16(float& c0, float& c1, float& c2, float& c3,
                                         uint32_t a0, uint32_t a1, uint32_t a2, uint32_t a3,
                                         uint32_t b0, uint32_t b1) {
    asm volatile(
        "mma.sync.aligned.m16n8k16.row.col.f32.bf16.bf16.f32 "
        "{%0,%1,%2,%3}, {%4,%5,%6,%7}, {%8,%9}, {%0,%1,%2,%3};"
        : "+f"(c0), "+f"(c1), "+f"(c2), "+f"(c3)
        : "r"(a0), "r"(a1), "r"(a2), "r"(a3), "r"(b0), "r"(b1));
}

// ---------------- (type,dst) CSR construction --------------------------------
__global__ void k_zero_cnt() {
    int i = blockIdx.x * blockDim.x + threadIdx.x;
    if (i < NSEG) g_cnt[i] = 0;
}

__global__ void k_count(const int* __restrict__ dst, const int* __restrict__ ety) {
    int e = blockIdx.x * blockDim.x + threadIdx.x;
    if (e < EE) atomicAdd(&g_cnt[ety[e] * NN + dst[e]], 1);
}

__global__ void k_scan_block() {
    __shared__ int sh[1024];
    int i = blockIdx.x * 1024 + threadIdx.x;
    int v = (i < NSEG) ? g_cnt[i] : 0;
    sh[threadIdx.x] = v;
    __syncthreads();
    for (int d = 1; d < 1024; d <<= 1) {
        int t = (threadIdx.x >= d) ? sh[threadIdx.x - d] : 0;
        __syncthreads();
        sh[threadIdx.x] += t;
        __syncthreads();
    }
    if (i < NSEG) g_offs[i] = sh[threadIdx.x] - v;   // exclusive
    if (threadIdx.x == 1023) g_aux[blockIdx.x] = sh[1023];
}

__global__ void k_scan_aux() {
    if (threadIdx.x == 0) {
        int s = 0;
        for (int i = 0; i < NB2; i++) { int t = g_aux[i]; g_aux[i] = s; s += t; }
    }
}

__global__ void k_add_aux() {
    int i = blockIdx.x * 1024 + threadIdx.x;
    if (i < NSEG) {
        int v = g_offs[i] + g_aux[blockIdx.x];
        g_offs[i] = v;
        g_cur[i]  = v;
    }
}

__global__ void k_scatter(const int* __restrict__ srcl, const int* __restrict__ dst,
                          const int* __restrict__ ety) {
    int e = blockIdx.x * blockDim.x + threadIdx.x;
    if (e < EE) {
        int pos = atomicAdd(&g_cur[ety[e] * NN + dst[e]], 1);
        g_src[pos] = srcl[e];
    }
}

// ---------------- weight transpose + bf16 hi/lo split -------------------------
__global__ void k_transW(const float* __restrict__ W1, const float* __restrict__ W2) {
    int i = blockIdx.x * blockDim.x + threadIdx.x;
    const int N1 = TT * HC1 * DD;   // 65536
    const int N2 = TT * HC2 * HC1;  // 32768
    if (i < N1) {
        int t = i >> 14, r = i & 16383;
        int n = r >> 7, k = r & 127;
        float v = W1[(t << 14) + k * HC1 + n];
        __nv_bfloat16 h = __float2bfloat16(v);
        gW1h[i] = h;
        gW1l[i] = __float2bfloat16(v - __bfloat162float(h));
    } else if (i < N1 + N2) {
        int j = i - N1;
        int t = j >> 13, r = j & 8191;
        int n = r >> 7, k = r & 127;
        float v = W2[t * 8192 + k * HC2 + n];
        __nv_bfloat16 h = __float2bfloat16(v);
        gW2h[j] = h;
        gW2l[j] = __float2bfloat16(v - __bfloat162float(h));
    }
}

__global__ void k_split_x(const float* __restrict__ x) {
    int i = blockIdx.x * blockDim.x + threadIdx.x;
    if (i < NN * DD) {
        float v = x[i];
        __nv_bfloat16 h = __float2bfloat16(v);
        g_xh[i] = h;
        g_xl[i] = __float2bfloat16(v - __bfloat162float(h));
    }
}

// ---------------- HMMA bf16-split GEMM (batched over t via grid.y) -----------
template <int NT>
__global__ void __launch_bounds__(256, 1)
k_gemm_mma(const __nv_bfloat16* __restrict__ Ah, const __nv_bfloat16* __restrict__ Al,
           size_t aTstride,
           const __nv_bfloat16* __restrict__ Bh, const __nv_bfloat16* __restrict__ Bl,
           float* __restrict__ C, int M) {
    constexpr int K    = 128;
    constexpr int STRB = 272;
    constexpr int ASZ  = 128 * STRB;
    constexpr int BSZ  = NT  * STRB;
    constexpr int NW   = NT / 4;
    constexpr int NF   = NW / 8;

    extern __shared__ __align__(16) char smem[];
    uint32_t sb = smem_u32(smem);
    const uint32_t As = sb;
    const uint32_t Bs = sb + 2 * ASZ;

    int tid = threadIdx.x, wid = tid >> 5, lane = tid & 31;
    int m0 = blockIdx.x * 128;
    int t = blockIdx.y;
    Ah += (size_t)t * aTstride;
    Al += (size_t)t * aTstride;
    Bh += (size_t)t * NT * K;
    Bl += (size_t)t * NT * K;
    C  += (size_t)t * NN * NT;

    {
        for (int idx = tid; idx < 128 * 16; idx += 256) {
            int row = idx >> 4, c = idx & 15;
            int gm = m0 + row;
            uint4 vh = make_uint4(0, 0, 0, 0), vl = vh;
            if (gm < M) {
                vh = *(const uint4*)&Ah[(size_t)gm * K + c * 8];
                vl = *(const uint4*)&Al[(size_t)gm * K + c * 8];
            }
            char* ph = smem + row * STRB + c * 16;
            *(uint4*)ph = vh;
            *(uint4*)(ph + ASZ) = vl;
        }
        for (int idx = tid; idx < NT * 16; idx += 256) {
            int row = idx >> 4, c = idx & 15;
            uint4 vh = *(const uint4*)&Bh[(size_t)row * K + c * 8];
            uint4 vl = *(const uint4*)&Bl[(size_t)row * K + c * 8];
            char* ph = smem + 2 * ASZ + row * STRB + c * 16;
            *(uint4*)ph = vh;
            *(uint4*)(ph + BSZ) = vl;
        }
    }
    __syncthreads();

    int warpM = wid >> 2;
    int warpN = wid & 3;
    int lr = lane & 7, lg = lane >> 3;

    uint32_t aRow = warpM * 64 + lr + (lg & 1) * 8;
    uint32_t aCol = (lg >> 1) * 8;
    uint32_t bRow = warpN * NW + lr + (lg >> 1) * 8;
    uint32_t bCol = (lg & 1) * 8;

    float c[4][NF][4];
#pragma unroll
    for (int mf = 0; mf < 4; mf++)
#pragma unroll
        for (int nf = 0; nf < NF; nf++)
#pragma unroll
            for (int j = 0; j < 4; j++) c[mf][nf][j] = 0.f;

#pragma unroll
    for (int p = 0; p < 3; p++) {
        uint32_t Abase = As + ((p == 2) ? ASZ : 0);
        uint32_t Bbase = Bs + ((p == 1) ? BSZ : 0);
#pragma unroll
        for (int ks = 0; ks < 8; ks++) {
            int k0 = ks * 16;
            uint32_t a[4][4];
#pragma unroll
            for (int mf = 0; mf < 4; mf++) {
                uint32_t ad = Abase + (aRow + mf * 16) * STRB + (k0 + aCol) * 2;
                LDMX4(a[mf][0], a[mf][1], a[mf][2], a[mf][3], ad);
            }
            uint32_t b[NF][2];
#pragma unroll
            for (int nf2 = 0; nf2 < NF / 2; nf2++) {
                uint32_t bd = Bbase + (bRow + nf2 * 16) * STRB + (k0 + bCol) * 2;
                uint32_t r0, r1, r2, r3;
                LDMX4(r0, r1, r2, r3, bd);
                b[2 * nf2][0] = r0; b[2 * nf2][1] = r1;
                b[2 * nf2 + 1][0] = r2; b[2 * nf2 + 1][1] = r3;
            }
#pragma unroll
            for (int mf = 0; mf < 4; mf++)
#pragma unroll
                for (int nf = 0; nf < NF; nf++)
                    mma_bf16(c[mf][nf][0], c[mf][nf][1], c[mf][nf][2], c[mf][nf][3],
                             a[mf][0], a[mf][1], a[mf][2], a[mf][3],
                             b[nf][0], b[nf][1]);
        }
    }

    int g = lane >> 2, tq = lane & 3;
#pragma unroll
    for (int mf = 0; mf < 4; mf++) {
        int m = m0 + warpM * 64 + mf * 16 + g;
#pragma unroll
        for (int nf = 0; nf < NF; nf++) {
            int n = warpN * NW + nf * 8 + tq * 2;
            if (m < M)
                *(float2*)&C[(size_t)m * NT + n] = make_float2(c[mf][nf][0], c[mf][nf][1]);
            if (m + 8 < M)
                *(float2*)&C[(size_t)(m + 8) * NT + n] = make_float2(c[mf][nf][2], c[mf][nf][3]);
        }
    }
}

// ---------------- attention score precompute (batched over t) ----------------
template <int C>
__global__ void k_scores(const float* __restrict__ feat,
                         const float* __restrict__ a_s, const float* __restrict__ a_d) {
    int idx = blockIdx.x * blockDim.x + threadIdx.x;
    if (idx >= TT * NN * HH) return;
    int tn = idx >> 3, hd = idx & 7;
    int t = tn / NN;
    const float* f = &feat[(size_t)tn * 8 * C + hd * C];
    const float* as = &a_s[(t * HH + hd) * C];
    const float* ad = &a_d[(t * HH + hd) * C];
    float s1 = 0.f, s2 = 0.f;
#pragma unroll
    for (int c4 = 0; c4 < C / 4; c4++) {
        float4 v = *(const float4*)&f[c4 * 4];
        float4 w1 = *(const float4*)&as[c4 * 4];
        float4 w2 = *(const float4*)&ad[c4 * 4];
        s1 += v.x * w1.x + v.y * w1.y + v.z * w1.z + v.w * w1.w;
        s2 += v.x * w2.x + v.y * w2.y + v.z * w2.z + v.w * w2.w;
    }
    g_ss[idx] = s1;
    g_sd[idx] = s2;
}

// ---------------- GAT aggregation: one warp per (type,node), online softmax --
template <int C, bool BF16OUT>
__global__ void k_gat(const float* __restrict__ featbase,
                      const float* __restrict__ biasbase,
                      float* __restrict__ outbase, int ostride, int ocol_step,
                      __nv_bfloat16* __restrict__ outh,
                      __nv_bfloat16* __restrict__ outl, int dorelu) {
    constexpr int HC = 8 * C;
    constexpr int VW = C / 4;               // 4 for C=16, 2 for C=8
    int seg = (blockIdx.x * blockDim.x + threadIdx.x) >> 5;
    if (seg >= NSEG) return;
    int lane = threadIdx.x & 31;
    int t = seg / NN;
    int node = seg - t * NN;
    int start = g_offs[seg];
    int deg   = g_cnt[seg];

    const float* feat = featbase + (size_t)t * NN * HC;
    const float* ssp  = g_ss + (size_t)t * NN * 8;
    const float* sdp  = g_sd + (size_t)t * NN * 8;
    const float* bias = biasbase + t * HC;

    int hd = lane >> 2;
    int cbase = (lane & 3) * VW;
    float sd_h = sdp[node * 8 + hd];

    // self-loop seeds the online softmax state
    float m = ssp[node * 8 + hd] + sd_h;
    m = m > 0.f ? m : LRELU * m;
    float denom = 1.f;

    float acc[VW];
    {
        const float* fp = &feat[(size_t)node * HC + hd * C + cbase];
        if constexpr (VW == 4) {
            float4 hv = *(const float4*)fp;
            acc[0] = hv.x; acc[1] = hv.y; acc[2] = hv.z; acc[3] = hv.w;
        } else {
            float2 hv = *(const float2*)fp;
            acc[0] = hv.x; acc[1] = hv.y;
        }
    }

    for (int i = 0; i < deg; i++) {
        int s = g_src[start + i];
        float u = ssp[s * 8 + hd] + sd_h;
        u = u > 0.f ? u : LRELU * u;
        float pe;
        if (u > m) {
            float r = __expf(m - u);
            denom = denom * r + 1.f;
#pragma unroll
            for (int j = 0; j < VW; j++) acc[j] *= r;
            m = u;
            pe = 1.f;
        } else {
            pe = __expf(u - m);
            denom += pe;
        }
        const float* fp = &feat[(size_t)s * HC + hd * C + cbase];
        if constexpr (VW == 4) {
            float4 hv = *(const float4*)fp;
            acc[0] += pe * hv.x; acc[1] += pe * hv.y;
            acc[2] += pe * hv.z; acc[3] += pe * hv.w;
        } else {
            float2 hv = *(const float2*)fp;
            acc[0] += pe * hv.x; acc[1] += pe * hv.y;
        }
    }

    float inv = 1.f / denom;
    float o[VW];
#pragma unroll
    for (int j = 0; j < VW; j++) {
        float v = acc[j] * inv + bias[hd * C + cbase + j];
        if (dorelu) v = fmaxf(v, 0.f);
        o[j] = v;
    }
    if constexpr (BF16OUT) {
        size_t ob = ((size_t)t * NN + node) * HC + hd * C + cbase;
#pragma unroll
        for (int j = 0; j < VW; j += 2) {
            __nv_bfloat16 h0 = __float2bfloat16(o[j]);
            __nv_bfloat16 h1b = __float2bfloat16(o[j + 1]);
            __nv_bfloat162 hp; hp.x = h0; hp.y = h1b;
            __nv_bfloat162 lp;
            lp.x = __float2bfloat16(o[j] - __bfloat162float(h0));
            lp.y = __float2bfloat16(o[j + 1] - __bfloat162float(h1b));
            *(__nv_bfloat162*)&outh[ob + j] = hp;
            *(__nv_bfloat162*)&outl[ob + j] = lp;
        }
    } else {
        float* op = &outbase[(size_t)node * ostride + t * ocol_step + hd * C + cbase];
        if constexpr (VW == 4) {
            *(float4*)op = make_float4(o[0], o[1], o[2], o[3]);
        } else {
            *(float2*)op = make_float2(o[0], o[1]);
        }
    }
}

// ---------------- launch ------------------------------------------------------
extern "C" void kernel_launch(void* const* d_in, const int* in_sizes, int n_in,
                              void* d_out, int out_size) {
    const float* x     = (const float*)d_in[0];
    const int*   esrc  = (const int*)  d_in[1];
    const int*   edst  = (const int*)  d_in[2];
    const int*   etype = (const int*)  d_in[3];
    const float* W1    = (const float*)d_in[4];
    const float* a1s   = (const float*)d_in[5];
    const float* a1d   = (const float*)d_in[6];
    const float* b1    = (const float*)d_in[7];
    const float* W2    = (const float*)d_in[8];
    const float* a2s   = (const float*)d_in[9];
    const float* a2d   = (const float*)d_in[10];
    const float* b2    = (const float*)d_in[11];
    float* out = (float*)d_out;

    float *p_h1, *p_h2;
    __nv_bfloat16 *pW1h, *pW1l, *pW2h, *pW2l, *p_xh, *p_xl, *p_h1gh, *p_h1gl;
    cudaGetSymbolAddress((void**)&p_h1,   g_h1);
    cudaGetSymbolAddress((void**)&p_h2,   g_h2);
    cudaGetSymbolAddress((void**)&pW1h,   gW1h);
    cudaGetSymbolAddress((void**)&pW1l,   gW1l);
    cudaGetSymbolAddress((void**)&pW2h,   gW2h);
    cudaGetSymbolAddress((void**)&pW2l,   gW2l);
    cudaGetSymbolAddress((void**)&p_xh,   g_xh);
    cudaGetSymbolAddress((void**)&p_xl,   g_xl);
    cudaGetSymbolAddress((void**)&p_h1gh, g_h1gh);
    cudaGetSymbolAddress((void**)&p_h1gl, g_h1gl);

    const int ASZ = 128 * 272;
    const int smem1 = 2 * ASZ + 2 * 128 * 272;   // 139264
    const int smem2 = 2 * ASZ + 2 * 64 * 272;    // 104448
    cudaFuncSetAttribute(k_gemm_mma<HC1>, cudaFuncAttributeMaxDynamicSharedMemorySize, smem1);
    cudaFuncSetAttribute(k_gemm_mma<HC2>, cudaFuncAttributeMaxDynamicSharedMemorySize, smem2);

    // --- (type,dst) CSR build ---
    k_zero_cnt<<<(NSEG + 255) / 256, 256>>>();
    k_count<<<(EE + 255) / 256, 256>>>(edst, etype);
    k_scan_block<<<NB2, 1024>>>();
    k_scan_aux<<<1, 32>>>();
    k_add_aux<<<NB2, 1024>>>();
    k_scatter<<<(EE + 255) / 256, 256>>>(esrc, edst, etype);

    // --- weight transpose + bf16 splits ---
    k_transW<<<(TT * HC1 * DD + TT * HC2 * HC1 + 255) / 256, 256>>>(W1, W2);
    k_split_x<<<(NN * DD + 255) / 256, 256>>>(x);

    const int gat_blocks = (NSEG * 32 + 255) / 256;
    const int sc_blocks  = (TT * NN * HH + 255) / 256;

    // layer 1 (all t): h1 = x @ W1[t]
    {
        dim3 grid(MTILES, TT);
        k_gemm_mma<HC1><<<grid, 256, smem1>>>(p_xh, p_xl, 0,
                                              pW1h, pW1l, p_h1, NN);
    }
    k_scores<C1V><<<sc_blocks, 256>>>(p_h1, a1s, a1d);
    k_gat<C1V, true><<<gat_blocks, 256>>>(p_h1, b1, nullptr, 0, 0,
                                          p_h1gh, p_h1gl, 1);
    // layer 2 (all t): h2 = h1g @ W2[t]
    {
        dim3 grid(MTILES, TT);
        k_gemm_mma<HC2><<<grid, 256, smem2>>>(p_h1gh, p_h1gl, (size_t)NN * HC1,
                                              pW2h, pW2l, p_h2, NN);
    }
    k_scores<C2V><<<sc_blocks, 256>>>(p_h2, a2s, a2d);
    k_gat<C2V, false><<<gat_blocks, 256>>>(p_h2, b2, out, OUTW, HC2,
                                           nullptr, nullptr, 0);
}